// round 9
// baseline (speedup 1.0000x reference)
#include <cuda_runtime.h>
#include <cuda_bf16.h>
#include <math.h>

// Fused HyperNet scoring (Lorentz invariance: tails never transformed):
//   out[b,n] = MARGIN - <t,t>_M - <h,h>_M + 2 * t . g_b
//              + tanh(bias_head[u_b]) + tanh(bias_tail[v_bn])
//   g_b = Q_t B_t G' B_h Q_h^T h_b
//
// One block per b, 288 threads:
//   warps 0-7 : score — issue pinned emb gathers FIRST (overlap everything)
//   all 9     : stage A — cooperatively gelu/normalize the 62 Householder rows
//               (+2 boost rows) into SMEM, 64 parallel row-reductions
//   warp 8    : the serial 62-step chain (one butterfly + FMA per step; the
//               w~ = sqrt(2/n2) w normalization removes the div from the chain)
//   warps 0-7 : after barrier, combine gathered tails with g, coalesced store.

#define DV   31
#define MARGIN_C 0.85f

static __device__ __forceinline__ float wsum(float v) {
#pragma unroll
    for (int o = 16; o > 0; o >>= 1)
        v += __shfl_xor_sync(0xffffffffu, v, o);
    return v;
}

static __device__ __forceinline__ float gelu_exact(float a) {
    return 0.5f * a * (1.0f + erff(a * 0.70710678118654752f));
}

// Pinned gather with L2 evict_last retention (createpolicy + cache_hint).
static __device__ __forceinline__ float4 ldg_evict_last_v4(const float4* p,
                                                           unsigned long long pol) {
    float4 v;
    asm volatile("ld.global.nc.L2::cache_hint.v4.f32 {%0,%1,%2,%3}, [%4], %5;"
                 : "=f"(v.x), "=f"(v.y), "=f"(v.z), "=f"(v.w)
                 : "l"(p), "l"(pol));
    return v;
}

__global__ void __launch_bounds__(288, 3) fused_kernel(
    const int* __restrict__ u_arr, const int* __restrict__ r_arr,
    const int* __restrict__ v_arr,
    const float* __restrict__ emb,
    const float* __restrict__ bias_head, const float* __restrict__ bias_tail,
    const float* __restrict__ hrw, const float* __restrict__ hbw,
    const float* __restrict__ trw, const float* __restrict__ tbw,
    float* __restrict__ out, int N)
{
    // rows 0-30: head rot w~ ; 31-61: tail rot w~ (tail row k at 31+k)
    // row 62: head boost ro ; row 63: tail boost ro
    __shared__ float sw[64][32];
    __shared__ float sv2[2];                       // |ro|^2 for head/tail boosts
    __shared__ __align__(16) float sg[32];         // 2*g
    __shared__ float scb;                          // MARGIN - hh + tanh(bias_head)

    int b    = blockIdx.x;
    int tid  = threadIdx.x;
    int lane = tid & 31;
    int warp = tid >> 5;
    int rr   = r_arr[b];

    unsigned long long pol;
    asm("createpolicy.fractional.L2::evict_last.b64 %0, 1.0;" : "=l"(pol));

    // ---------------- score warps: issue batch-0 loads immediately ----------
    int q   = lane & 7;          // quad within row
    int grp = lane >> 3;         // which of the 4 rows this iteration
    const float4* emb4 = (const float4*)emb;
    const int* vrow = v_arr + (size_t)b * N;
    float* orow = out + (size_t)b * N;

    int    idxs[8];
    float4 tvs[8];
    float  bts[8];
    int base0 = warp * 32;
    bool score_w = (warp < 8);
    if (score_w) {
#pragma unroll
        for (int it = 0; it < 8; ++it) {
            int n = base0 + it * 4 + grp;
            idxs[it] = (n < N) ? vrow[n] : 0;
        }
#pragma unroll
        for (int it = 0; it < 8; ++it)
            bts[it] = (q == 0) ? bias_tail[idxs[it]] : 0.0f;
#pragma unroll
        for (int it = 0; it < 8; ++it)
            tvs[it] = ldg_evict_last_v4(emb4 + (size_t)idxs[it] * 8 + q, pol);
    }

    // ---------------- prep warp: early head loads ---------------------------
    float x = 0.0f, bh = 0.0f;
    if (warp == 8) {
        int uu = u_arr[b];
        x  = emb[(size_t)uu * 32 + lane];
        bh = bias_head[uu];
    }

    // ---------------- stage A: cooperative weight prep (all 9 warps) --------
    {
        const float* hb_ = hrw + (size_t)rr * (DV * DV);
        const float* tb_ = trw + (size_t)rr * (DV * DV);
        for (int j = warp; j < 64; j += 9) {
            float val = 0.0f;
            if (lane >= 1) {
                if (j < 31)       val = gelu_exact(hb_[j * DV + lane - 1]);
                else if (j < 62)  val = gelu_exact(tb_[(j - 31) * DV + lane - 1]);
                else if (j == 62) val = tanhf(hbw[(size_t)rr * DV + lane - 1]) * (1.0f / 32.0f);
                else              val = tanhf(tbw[(size_t)rr * DV + lane - 1]) * (1.0f / 32.0f);
            }
            float n2 = wsum(val * val);
            if (j < 62) {
                val *= sqrtf(2.0f) * rsqrtf(n2);   // w~ : H = I - w~ w~^T
            } else if (lane == 0) {
                sv2[j - 62] = n2;
            }
            sw[j][lane] = val;
        }
    }
    __syncthreads();

    // ---------------- warp 8: serial Lorentz chain --------------------------
    if (warp == 8) {
        float h0 = __shfl_sync(0xffffffffu, x, 0);
        float hh = wsum(x * x) - 2.0f * h0 * h0;

        // head rotation: H_0 .. H_30  (= Q_h^T h)
#pragma unroll
        for (int k = 0; k < DV; k++) {
            float w = sw[k][lane];
            float d = wsum(w * x);
            x -= d * w;
        }
        // head boost
        {
            float ro = sw[62][lane];
            float v2 = sv2[0];
            float zeta = __fdividef(1.0f, sqrtf(1.0f - v2) + 1e-8f);
            float c2   = __fdividef(zeta - 1.0f, v2 + 1e-9f);
            float dot  = wsum(ro * x);
            float x0   = __shfl_sync(0xffffffffu, x, 0);
            x = (lane == 0) ? (zeta * x0 - zeta * dot)
                            : (-zeta * x0 * ro + x + c2 * ro * dot);
        }
        // G' = diag(-1, 1, ..., 1)
        if (lane == 0) x = -x;
        // tail boost (symmetric)
        {
            float ro = sw[63][lane];
            float v2 = sv2[1];
            float zeta = __fdividef(1.0f, sqrtf(1.0f - v2) + 1e-8f);
            float c2   = __fdividef(zeta - 1.0f, v2 + 1e-9f);
            float dot  = wsum(ro * x);
            float x0   = __shfl_sync(0xffffffffu, x, 0);
            x = (lane == 0) ? (zeta * x0 - zeta * dot)
                            : (-zeta * x0 * ro + x + c2 * ro * dot);
        }
        // tail rotation: H_30 .. H_0  (= Q_t x)
#pragma unroll
        for (int k = DV - 1; k >= 0; k--) {
            float w = sw[31 + k][lane];
            float d = wsum(w * x);
            x -= d * w;
        }

        sg[lane] = 2.0f * x;
        if (lane == 0) scb = MARGIN_C - hh + tanhf(bh);
    }
    __syncthreads();

    // ---------------- score warps: combine + coalesced store ----------------
    float4 gq = ((const float4*)sg)[q];
    float  cb = scb;

    if (score_w) {
        float vals[8];
#pragma unroll
        for (int it = 0; it < 8; ++it) {
            float4 tv = tvs[it];
            float val = tv.x * (gq.x - tv.x) + tv.y * (gq.y - tv.y)
                      + tv.z * (gq.z - tv.z) + tv.w * (gq.w - tv.w);
            if (q == 0) val += 2.0f * tv.x * tv.x;
            val += __shfl_xor_sync(0xffffffffu, val, 1);
            val += __shfl_xor_sync(0xffffffffu, val, 2);
            val += __shfl_xor_sync(0xffffffffu, val, 4);
            vals[it] = val + cb + tanhf(bts[it]);  // complete at q==0 lanes
        }
        // transpose: lane L takes row base0+L from iteration L>>2, lane (L&3)*8
        float outv = 0.0f;
#pragma unroll
        for (int it = 0; it < 8; ++it) {
            float t = __shfl_sync(0xffffffffu, vals[it], (lane & 3) << 3);
            if ((lane >> 2) == it) outv = t;
        }
        int n = base0 + lane;
        if (n < N) orow[n] = outv;    // 128B coalesced per warp

        // remaining tiles (not taken when N == 256)
        for (int base = 256 + warp * 32; base < N; base += 256) {
#pragma unroll
            for (int it = 0; it < 8; ++it) {
                int nn = base + it * 4 + grp;
                idxs[it] = (nn < N) ? vrow[nn] : 0;
            }
#pragma unroll
            for (int it = 0; it < 8; ++it)
                bts[it] = (q == 0) ? bias_tail[idxs[it]] : 0.0f;
#pragma unroll
            for (int it = 0; it < 8; ++it)
                tvs[it] = ldg_evict_last_v4(emb4 + (size_t)idxs[it] * 8 + q, pol);
#pragma unroll
            for (int it = 0; it < 8; ++it) {
                float4 tv = tvs[it];
                float val = tv.x * (gq.x - tv.x) + tv.y * (gq.y - tv.y)
                          + tv.z * (gq.z - tv.z) + tv.w * (gq.w - tv.w);
                if (q == 0) val += 2.0f * tv.x * tv.x;
                val += __shfl_xor_sync(0xffffffffu, val, 1);
                val += __shfl_xor_sync(0xffffffffu, val, 2);
                val += __shfl_xor_sync(0xffffffffu, val, 4);
                vals[it] = val + cb + tanhf(bts[it]);
            }
            float outv2 = 0.0f;
#pragma unroll
            for (int it = 0; it < 8; ++it) {
                float t = __shfl_sync(0xffffffffu, vals[it], (lane & 3) << 3);
                if ((lane >> 2) == it) outv2 = t;
            }
            int n2i = base + lane;
            if (n2i < N) orow[n2i] = outv2;
        }
    }
}

extern "C" void kernel_launch(void* const* d_in, const int* in_sizes, int n_in,
                              void* d_out, int out_size) {
    const int*   u         = (const int*)  d_in[0];
    const int*   r         = (const int*)  d_in[1];
    const int*   v         = (const int*)  d_in[2];
    const float* emb       = (const float*)d_in[3];
    const float* bias_head = (const float*)d_in[4];
    const float* bias_tail = (const float*)d_in[5];
    const float* hrw       = (const float*)d_in[6];
    const float* hbw       = (const float*)d_in[7];
    const float* trw       = (const float*)d_in[8];
    const float* tbw       = (const float*)d_in[9];
    float* out = (float*)d_out;

    int B = in_sizes[0];
    int N = in_sizes[2] / B;

    fused_kernel<<<B, 288>>>(u, r, v, emb, bias_head, bias_tail,
                             hrw, hbw, trw, tbw, out, N);
}

// round 11
// speedup vs baseline: 1.6883x; 1.6883x over previous
#include <cuda_runtime.h>
#include <cuda_bf16.h>
#include <math.h>

// out[b,n] = MARGIN - <t,t>_M - <h,h>_M + 2 * t . g_b
//            + tanh(bias_head[u_b]) + tanh(bias_tail[v_bn])
// g_b = Q_t B_t G' B_h Q_h^T h_b  (Lorentz invariance: tails never transformed)

#define DIMV 32
#define DV   31
#define MARGIN_C 0.85f

__device__ float g_buf[4096 * DIMV];
__device__ float c_buf[4096];

static __device__ __forceinline__ float wsum(float v) {
#pragma unroll
    for (int o = 16; o > 0; o >>= 1)
        v += __shfl_xor_sync(0xffffffffu, v, o);
    return v;
}

static __device__ __forceinline__ float gelu_exact(float a) {
    return 0.5f * a * (1.0f + erff(a * 0.70710678118654752f));
}

// 4 warps per block, one sample b per warp (pure R3 per-warp body).
// Lane l holds component l (lane 0 = time component). All weights prefetched
// into registers (MLP~62) and gelu/tanh'd before the serial 62-step chain.
__global__ void __launch_bounds__(128) prep_kernel(
    const int* __restrict__ u_arr, const int* __restrict__ r_arr,
    const float* __restrict__ emb, const float* __restrict__ bias_head,
    const float* __restrict__ hrw, const float* __restrict__ hbw,
    const float* __restrict__ trw, const float* __restrict__ tbw,
    int B)
{
    int b = blockIdx.x * 4 + (threadIdx.x >> 5);
    if (b >= B) return;
    int lane = threadIdx.x & 31;

    int uu = u_arr[b];
    int rr = r_arr[b];

    // ---- prefetch everything (independent LDGs, huge MLP) ----
    float hwr[DV], twr[DV];
    {
        const float* hb_ = hrw + (size_t)rr * (DV * DV);
        const float* tb_ = trw + (size_t)rr * (DV * DV);
#pragma unroll
        for (int k = 0; k < DV; k++) {
            hwr[k] = (lane >= 1) ? hb_[k * DV + (lane - 1)] : 0.0f;
            twr[k] = (lane >= 1) ? tb_[k * DV + (lane - 1)] : 0.0f;
        }
    }
    float hboost_raw = (lane >= 1) ? hbw[(size_t)rr * DV + (lane - 1)] : 0.0f;
    float tboost_raw = (lane >= 1) ? tbw[(size_t)rr * DV + (lane - 1)] : 0.0f;
    float x  = emb[(size_t)uu * DIMV + lane];
    float bh = bias_head[uu];

    // ---- nonlinearities off the critical chain ----
#pragma unroll
    for (int k = 0; k < DV; k++) hwr[k] = gelu_exact(hwr[k]);
#pragma unroll
    for (int k = 0; k < DV; k++) twr[k] = gelu_exact(twr[k]);
    float hro = tanhf(hboost_raw) * (1.0f / 32.0f);
    float tro = tanhf(tboost_raw) * (1.0f / 32.0f);

    // ---- norms: 62 independent reductions, pipelined (ILP), then fast div ----
    float hinv[DV], tinv[DV];
#pragma unroll
    for (int k = 0; k < DV; k++) { hinv[k] = hwr[k] * hwr[k]; tinv[k] = twr[k] * twr[k]; }
#pragma unroll
    for (int o = 16; o > 0; o >>= 1) {
#pragma unroll
        for (int k = 0; k < DV; k++) {
            hinv[k] += __shfl_xor_sync(0xffffffffu, hinv[k], o);
            tinv[k] += __shfl_xor_sync(0xffffffffu, tinv[k], o);
        }
    }
#pragma unroll
    for (int k = 0; k < DV; k++) {
        hinv[k] = __fdividef(2.0f, hinv[k]);
        tinv[k] = __fdividef(2.0f, tinv[k]);
    }

    // ---- boost coefficients (independent of x) ----
    float hv2 = wsum(hro * hro);
    float tv2 = wsum(tro * tro);
    float hzeta = __fdividef(1.0f, sqrtf(1.0f - hv2) + 1e-8f);
    float tzeta = __fdividef(1.0f, sqrtf(1.0f - tv2) + 1e-8f);
    float hc2 = __fdividef(hzeta - 1.0f, hv2 + 1e-9f);
    float tc2 = __fdividef(tzeta - 1.0f, tv2 + 1e-9f);

    // ---- <h,h>_M ----
    float h0 = __shfl_sync(0xffffffffu, x, 0);
    float hh = wsum(x * x) - 2.0f * h0 * h0;

    // ---- head rotation: apply H_0 .. H_30 (= Q_h^T x) ----
#pragma unroll
    for (int k = 0; k < DV; k++) {
        float d = wsum(hwr[k] * x);
        x -= (d * hinv[k]) * hwr[k];
    }
    // ---- head boost ----
    {
        float dot = wsum(hro * x);
        float x0  = __shfl_sync(0xffffffffu, x, 0);
        x = (lane == 0) ? (hzeta * x0 - hzeta * dot)
                        : (-hzeta * x0 * hro + x + hc2 * hro * dot);
    }
    // ---- G' ----
    if (lane == 0) x = -x;
    // ---- tail boost (symmetric) ----
    {
        float dot = wsum(tro * x);
        float x0  = __shfl_sync(0xffffffffu, x, 0);
        x = (lane == 0) ? (tzeta * x0 - tzeta * dot)
                        : (-tzeta * x0 * tro + x + tc2 * tro * dot);
    }
    // ---- tail rotation: apply H_30 .. H_0 (= Q_t x) ----
#pragma unroll
    for (int k = DV - 1; k >= 0; k--) {
        float d = wsum(twr[k] * x);
        x -= (d * tinv[k]) * twr[k];
    }

    g_buf[(size_t)b * DIMV + lane] = 2.0f * x;
    if (lane == 0)
        c_buf[b] = MARGIN_C - hh + tanhf(bh);
}

// Forced-in-flight gather with L2 evict_last retention (createpolicy +
// cache_hint). asm volatile pins all 8 loads in flight before any consumer.
static __device__ __forceinline__ float4 ldg_evict_last_v4(const float4* p,
                                                           unsigned long long pol) {
    float4 v;
    asm volatile("ld.global.nc.L2::cache_hint.v4.f32 {%0,%1,%2,%3}, [%4], %5;"
                 : "=f"(v.x), "=f"(v.y), "=f"(v.z), "=f"(v.w)
                 : "l"(p), "l"(pol));
    return v;
}

// R6 score body (12.8us measured — best known). One block (256 threads = 8
// warps) per b; each warp owns 32 contiguous output rows. 8 lanes per row.
// All 8 gathers per thread pinned in flight; results shuffle-transposed into
// one 128B coalesced store per warp.
__global__ void __launch_bounds__(256) score_kernel(
    const int* __restrict__ v_arr, const float* __restrict__ emb,
    const float* __restrict__ bias_tail,
    float* __restrict__ out, int N)
{
    int b = blockIdx.x;
    __shared__ float4 g4s[8];
    __shared__ float  cbs;

    unsigned long long pol;
    asm("createpolicy.fractional.L2::evict_last.b64 %0, 1.0;" : "=l"(pol));

    int tid = threadIdx.x;
    if (tid < 8) g4s[tid] = ((const float4*)(g_buf + (size_t)b * DIMV))[tid];
    if (tid == 0) cbs = c_buf[b];
    __syncthreads();

    int lane = tid & 31;
    int warp = tid >> 5;
    int q    = lane & 7;
    int grp  = lane >> 3;
    float4 gq = g4s[q];
    float  cb = cbs;

    const float4* emb4 = (const float4*)emb;
    const int* vrow = v_arr + (size_t)b * N;
    float* orow = out + (size_t)b * N;

    for (int base = warp * 32; base < N; base += 256) {
        int idxs[8];
#pragma unroll
        for (int it = 0; it < 8; ++it) {
            int n = base + it * 4 + grp;
            idxs[it] = (n < N) ? vrow[n] : 0;
        }
        // all 8 gathers pinned in flight (asm volatile, issue order preserved)
        float4 tvs[8];
#pragma unroll
        for (int it = 0; it < 8; ++it)
            tvs[it] = ldg_evict_last_v4(emb4 + (size_t)idxs[it] * 8 + q, pol);
        float bts[8];
#pragma unroll
        for (int it = 0; it < 8; ++it)
            bts[it] = (q == 0) ? bias_tail[idxs[it]] : 0.0f;

        float vals[8];
#pragma unroll
        for (int it = 0; it < 8; ++it) {
            float4 tv = tvs[it];
            float val = tv.x * (gq.x - tv.x) + tv.y * (gq.y - tv.y)
                      + tv.z * (gq.z - tv.z) + tv.w * (gq.w - tv.w);
            if (q == 0) val += 2.0f * tv.x * tv.x;
            val += __shfl_xor_sync(0xffffffffu, val, 1);
            val += __shfl_xor_sync(0xffffffffu, val, 2);
            val += __shfl_xor_sync(0xffffffffu, val, 4);
            vals[it] = val + cb + tanhf(bts[it]);   // complete at q==0 lanes
        }

        // transpose: lane L takes row base+L from iteration L>>2, lane (L&3)*8
        float outv = 0.0f;
#pragma unroll
        for (int it = 0; it < 8; ++it) {
            float t = __shfl_sync(0xffffffffu, vals[it], (lane & 3) << 3);
            if ((lane >> 2) == it) outv = t;
        }
        int n = base + lane;
        if (n < N) orow[n] = outv;   // 128B coalesced per warp
    }
}

extern "C" void kernel_launch(void* const* d_in, const int* in_sizes, int n_in,
                              void* d_out, int out_size) {
    const int*   u         = (const int*)  d_in[0];
    const int*   r         = (const int*)  d_in[1];
    const int*   v         = (const int*)  d_in[2];
    const float* emb       = (const float*)d_in[3];
    const float* bias_head = (const float*)d_in[4];
    const float* bias_tail = (const float*)d_in[5];
    const float* hrw       = (const float*)d_in[6];
    const float* hbw       = (const float*)d_in[7];
    const float* trw       = (const float*)d_in[8];
    const float* tbw       = (const float*)d_in[9];
    float* out = (float*)d_out;

    int B = in_sizes[0];
    int N = in_sizes[2] / B;

    prep_kernel<<<(B + 3) / 4, 128>>>(u, r, emb, bias_head, hrw, hbw, trw, tbw, B);
    score_kernel<<<B, 256>>>(v, emb, bias_tail, out, N);
}